// round 14
// baseline (speedup 1.0000x reference)
#include <cuda_runtime.h>
#include <cuda_bf16.h>
#include <cstdint>
#include <cstddef>

#define BB   16
#define WW   64
#define VV   64
#define DD   256
#define RR   64
#define NN   (WW*VV)
#define PAD  68

typedef unsigned long long ull;

__device__ float g_A   [BB*WW*DD];
__device__ float g_BtT [BB*DD*VV];
__device__ float g_relaT[DD*RR];
__device__ float g_AW  [BB*WW*DD];
__device__ float g_BW  [BB*VV*DD];
__device__ float g_RW  [RR*DD];
__device__ uint32_t g_w1bT [DD*DD/2];
__device__ uint32_t g_rwbHi[DD*RR/2];
__device__ __nv_bfloat16 g_tvh[(size_t)BB*NN*DD];
__device__ float g_att [BB*NN];
__device__ float g_fuse[BB*DD];

__device__ __forceinline__ float tanh_fast(float x) {
    float y; asm("tanh.approx.f32 %0, %1;" : "=f"(y) : "f"(x)); return y;
}
__device__ __forceinline__ ull fma2(ull a, ull b, ull c) {
    ull d; asm("fma.rn.f32x2 %0, %1, %2, %3;" : "=l"(d) : "l"(a), "l"(b), "l"(c)); return d;
}
__device__ __forceinline__ ull pack2(float x) {
    ull r; asm("mov.b64 %0, {%1, %1};" : "=l"(r) : "f"(x)); return r;
}
__device__ __forceinline__ float2 unpack2(ull v) {
    float2 f; asm("mov.b64 {%0, %1}, %2;" : "=f"(f.x), "=f"(f.y) : "l"(v)); return f;
}
__device__ __forceinline__ uint32_t smem_u32(const void* p) {
    uint32_t a;
    asm("{ .reg .u64 tmp; cvta.to.shared.u64 tmp, %1; cvt.u32.u64 %0, tmp; }" : "=r"(a) : "l"(p));
    return a;
}
__device__ __forceinline__ void cp_async16(uint32_t daddr, const void* src) {
    asm volatile("cp.async.cg.shared.global [%0], [%1], 16;" :: "r"(daddr), "l"(src) : "memory");
}
#define CP_COMMIT() asm volatile("cp.async.commit_group;" ::: "memory")
#define CP_WAIT0()  asm volatile("cp.async.wait_group 0;" ::: "memory")
#define CP_WAIT1()  asm volatile("cp.async.wait_group 1;" ::: "memory")

__device__ __forceinline__ void mma_bf16(float c[4],
    uint32_t a0, uint32_t a1, uint32_t a2, uint32_t a3, uint32_t b0, uint32_t b1)
{
    asm volatile(
        "mma.sync.aligned.m16n8k16.row.col.f32.bf16.bf16.f32 "
        "{%0,%1,%2,%3}, {%4,%5,%6,%7}, {%8,%9}, {%0,%1,%2,%3};"
        : "+f"(c[0]), "+f"(c[1]), "+f"(c[2]), "+f"(c[3])
        : "r"(a0), "r"(a1), "r"(a2), "r"(a3), "r"(b0), "r"(b1));
}
__device__ __forceinline__ uint32_t pkbf2(float a, float b) {
    return (uint32_t)__bfloat16_as_ushort(__float2bfloat16_rn(a))
         | ((uint32_t)__bfloat16_as_ushort(__float2bfloat16_rn(b)) << 16);
}

__global__ __launch_bounds__(256) void kW1T(const float* __restrict__ aw1)
{
    const int p = blockIdx.x, n = threadIdx.x;
    g_w1bT[n * 128 + p] = pkbf2(aw1[(2 * p) * DD + n], aw1[(2 * p + 1) * DD + n]);
}

__global__ __launch_bounds__(256) void kRWT()
{
    const int p = blockIdx.x, n = threadIdx.x;
    g_rwbHi[n * 32 + p] = pkbf2(g_RW[(2 * p) * DD + n], g_RW[(2 * p + 1) * DD + n]);
}

__global__ __launch_bounds__(256) void kPre(
    const int* __restrict__ head, const int* __restrict__ tail,
    const float* __restrict__ emb, const float* __restrict__ rela,
    const float* __restrict__ fc_w, const float* __restrict__ fc_b)
{
    __shared__ float sX[16][257];
    const int g = blockIdx.x, t = threadIdx.x;
    const int kind = (g < 64) ? 0 : (g < 128 ? 1 : 2);
    const int row0 = ((kind == 0) ? g : (kind == 1) ? (g - 64) : (g - 128)) * 16;

    #pragma unroll 4
    for (int rr = 0; rr < 16; ++rr) {
        const int row = row0 + rr;
        float v;
        if (kind == 0)      v = emb[(size_t)head[row] * DD + t];
        else if (kind == 1) v = emb[(size_t)tail[row] * DD + t];
        else                v = rela[row * DD + t];
        sX[rr][t] = v;
        if (kind == 0) g_A[row * DD + t] = v;
    }
    __syncthreads();

    const float* Wp = fc_w + (size_t)kind * DD * DD;
    float acc[16];
    #pragma unroll
    for (int r = 0; r < 16; ++r) acc[r] = (kind == 0) ? fc_b[t] : 0.0f;
    #pragma unroll 4
    for (int k = 0; k < DD; ++k) {
        const float wv = Wp[k * DD + t];
        #pragma unroll
        for (int r = 0; r < 16; ++r) acc[r] = fmaf(sX[r][k], wv, acc[r]);
    }
    float* dst = (kind == 0) ? g_AW : (kind == 1) ? g_BW : g_RW;
    #pragma unroll
    for (int r = 0; r < 16; ++r) dst[(row0 + r) * DD + t] = acc[r];

    if (kind != 0) {
        float* dstT = (kind == 1)
            ? (g_BtT + (size_t)(row0 >> 6) * DD * VV + (row0 & 63))
            : (g_relaT + row0);
        #pragma unroll
        for (int it = 0; it < 4; ++it) {
            const int f = it * 256 + t;
            const int d = f >> 2, q = f & 3;
            float4 v;
            v.x = sX[q * 4 + 0][d]; v.y = sX[q * 4 + 1][d];
            v.z = sX[q * 4 + 2][d]; v.w = sX[q * 4 + 3][d];
            *(float4*)&dstT[d * 64 + q * 4] = v;
        }
    }
}

// ---------------------------------------------------------------------------
// kMain: 1024 blocks x 256, 3 CTAs/SM (smem 66304 B, regs <=84).
// RA (4736 floats) reused: GEMM1 4x[16][68] -> RW 2x slice -> w1 [32][132]u32
// Softmax fully in registers (no sP).
// ---------------------------------------------------------------------------
#define SM_RA    0
#define SM_PAH   4736
#define SM_AH    7040
#define SM_SA    15488
#define SM_SAW   15744
#define SM_SB1   16000
#define SM_SW2   16256
#define SM_SRED  16512
#define SMEM_M_FLOATS 16576
#define SMEM_M_BYTES  (SMEM_M_FLOATS * 4)

__global__ __launch_bounds__(256, 3) void kMain(
    const float* __restrict__ att_b1, const float* __restrict__ att_w2,
    const float* __restrict__ att_b2, float* __restrict__ out_ns)
{
    const int t  = threadIdx.x;
    const int b  = blockIdx.x >> 6;
    const int i  = blockIdx.x & 63;
    const int lane = t & 31, wid = t >> 5;
    const int tx = t & 15, ty = t >> 4;
    const int j0g = ty * 4, r0 = tx * 4;
    const int gid = lane >> 2, tid4 = lane & 3;
    const int wm  = (wid & 3) * 16;
    const int wnl = (wid >> 2) * 32;      // GEMM2 warp n-offset (64-col chunks)
    const int wn2 = (wid >> 2) * 16;      // GEMM3 warp n-offset (32-col chunks)

    extern __shared__ float sm[];
    float*    sRA  = sm + SM_RA;
    uint32_t* sPAH = (uint32_t*)(sm + SM_PAH);   // [64][36]
    uint32_t* sAhi = (uint32_t*)(sm + SM_AH);    // [64][132]
    float*    sA   = sm + SM_SA;
    float*    sAW  = sm + SM_SAW;
    float*    sb1  = sm + SM_SB1;
    float*    sw2  = sm + SM_SW2;
    float*    sred = sm + SM_SRED;

    const int rowA = b * WW + i;
    sA [t] = g_A [rowA * DD + t];
    sAW[t] = g_AW[rowA * DD + t];
    sb1[t] = att_b1[t];
    sw2[t] = att_w2[t];
    __syncthreads();

    // ---- GEMM1: scalar fp32, 16 k-chunks of 16d, pipelined fills ----
    const float* btT = g_BtT + (size_t)b * DD * VV;
    float* hb[2] = { sRA, sRA + 2176 };
    float* rb[2] = { sRA + 1088, sRA + 3264 };
    const int fd = t >> 4;            // 0..15
    const int fc = (t & 15) * 4;

    float4 hpre;
    {
        float4 v = *(const float4*)(btT + fd * 64 + fc);
        const float sa = sA[fd];
        v.x *= sa; v.y *= sa; v.z *= sa; v.w *= sa;
        *(float4*)&hb[0][fd * PAD + fc] = v;
        hpre = *(const float4*)(btT + (16 + fd) * 64 + fc);
        cp_async16(smem_u32(rb[0]) + (uint32_t)(fd * PAD + fc) * 4, g_relaT + fd * 64 + fc);
        CP_COMMIT();
        cp_async16(smem_u32(rb[1]) + (uint32_t)(fd * PAD + fc) * 4, g_relaT + (16 + fd) * 64 + fc);
        CP_COMMIT();
    }

    ull c1[4][2];
    #pragma unroll
    for (int u = 0; u < 4; ++u) { c1[u][0] = 0ull; c1[u][1] = 0ull; }

    for (int kc = 0; kc < 16; ++kc) {
        if (kc < 15) { CP_WAIT1(); } else { CP_WAIT0(); }
        __syncthreads();
        const float* hh = hb[kc & 1];
        const float* rr = rb[kc & 1];
        #pragma unroll 4
        for (int d = 0; d < 16; ++d) {
            const float4 h4 = *(const float4*)&hh[d * PAD + j0g];
            const ulonglong2 r2 = *(const ulonglong2*)&rr[d * PAD + r0];
            const ull hp[4] = {pack2(h4.x), pack2(h4.y), pack2(h4.z), pack2(h4.w)};
            #pragma unroll
            for (int u = 0; u < 4; ++u) {
                c1[u][0] = fma2(hp[u], r2.x, c1[u][0]);
                c1[u][1] = fma2(hp[u], r2.y, c1[u][1]);
            }
        }
        __syncthreads();
        if (kc < 15) {
            float* hd = hb[(kc + 1) & 1];
            const float sa = sA[(kc + 1) * 16 + fd];
            float4 v = hpre;
            v.x *= sa; v.y *= sa; v.z *= sa; v.w *= sa;
            *(float4*)&hd[fd * PAD + fc] = v;
            if (kc < 14) {
                hpre = *(const float4*)(btT + ((kc + 2) * 16 + fd) * 64 + fc);
                cp_async16(smem_u32(rb[kc & 1]) + (uint32_t)(fd * PAD + fc) * 4,
                           g_relaT + ((kc + 2) * 16 + fd) * 64 + fc);
                CP_COMMIT();
            }
        }
    }

    // RA free now: issue RW-hi slices 0,1 ([64][36]u32 each)
    uint32_t* rwBuf[2] = { (uint32_t*)sRA, (uint32_t*)sRA + 2304 };
    #pragma unroll
    for (int s = 0; s < 2; ++s) {
        const uint32_t hB = smem_u32(rwBuf[s]);
        #pragma unroll
        for (int it = 0; it < 2; ++it) {
            const int idx = it * 256 + t;       // 512 uint4
            const int n  = idx >> 3;
            const int q4 = (idx & 7) * 4;
            cp_async16(hB + (uint32_t)(n * 144 + q4 * 4), g_rwbHi + (s * 64 + n) * 32 + q4);
        }
        CP_COMMIT();
    }

    // ---- softmax fully in registers ----
    float P[4][4];
    #pragma unroll
    for (int u = 0; u < 4; ++u) {
        const float2 lo = unpack2(c1[u][0]);
        const float2 hi = unpack2(c1[u][1]);
        P[u][0] = lo.x; P[u][1] = lo.y; P[u][2] = hi.x; P[u][3] = hi.y;
    }
    const int nulLane = (lane & 16) | 15;
    #pragma unroll
    for (int u = 0; u < 4; ++u) {
        const float nul = __shfl_sync(0xffffffffu, P[u][3], nulLane);
        float mx = -1e30f;
        #pragma unroll
        for (int v = 0; v < 4; ++v) {
            P[u][v] = (P[u][v] <= nul) ? -1e10f : P[u][v];
            mx = fmaxf(mx, P[u][v]);
        }
        mx = fmaxf(mx, __shfl_xor_sync(0xffffffffu, mx, 1));
        mx = fmaxf(mx, __shfl_xor_sync(0xffffffffu, mx, 2));
        mx = fmaxf(mx, __shfl_xor_sync(0xffffffffu, mx, 4));
        mx = fmaxf(mx, __shfl_xor_sync(0xffffffffu, mx, 8));
        float se = 0.0f;
        #pragma unroll
        for (int v = 0; v < 4; ++v) { P[u][v] = expf(P[u][v] - mx); se += P[u][v]; }
        se += __shfl_xor_sync(0xffffffffu, se, 1);
        se += __shfl_xor_sync(0xffffffffu, se, 2);
        se += __shfl_xor_sync(0xffffffffu, se, 4);
        se += __shfl_xor_sync(0xffffffffu, se, 8);
        const float inv = 1.0f / se;
        #pragma unroll
        for (int v = 0; v < 4; ++v) P[u][v] *= inv;
    }

    // write norm_scores + pack P pairs into sPAH
    const size_t ns_base = ((size_t)(b * NN + i * VV)) * RR;
    #pragma unroll
    for (int u = 0; u < 4; ++u) {
        *(float4*)&out_ns[ns_base + (size_t)(j0g + u) * RR + r0] =
            make_float4(P[u][0], P[u][1], P[u][2], P[u][3]);
        sPAH[(j0g + u) * 36 + tx * 2 + 0] = pkbf2(P[u][0], P[u][1]);
        sPAH[(j0g + u) * 36 + tx * 2 + 1] = pkbf2(P[u][2], P[u][3]);
    }

    // ---- GEMM2: PV = P @ RW, bf16, 4 n-chunks of 64 (RW double-buffered) ----
    const int pr0 = (wm + gid) * 36;
    const int pr1 = (wm + gid + 8) * 36;
    const int row0 = wm + gid, row1 = wm + gid + 8;
    const size_t tvb0 = ((size_t)(b * NN + i * VV + row0)) * DD;
    const size_t tvb1 = ((size_t)(b * NN + i * VV + row1)) * DD;
    const float* bwr0 = g_BW + (size_t)(b * VV + row0) * DD;
    const float* bwr1 = g_BW + (size_t)(b * VV + row1) * DD;
    uint32_t* tvu = (uint32_t*)g_tvh;

    for (int c = 0; c < 4; ++c) {
        if (c == 3) { CP_WAIT0(); } else { CP_WAIT1(); }
        __syncthreads();
        const uint32_t* rwH = rwBuf[c & 1];

        float a2[4][4];
        #pragma unroll
        for (int nt = 0; nt < 4; ++nt)
            #pragma unroll
            for (int e = 0; e < 4; ++e) a2[nt][e] = 0.0f;

        #pragma unroll
        for (int ks = 0; ks < 4; ++ks) {
            const int gp = ks * 8 + tid4;
            const uint32_t h0 = sPAH[pr0 + gp];
            const uint32_t h1 = sPAH[pr1 + gp];
            const uint32_t h2 = sPAH[pr0 + gp + 4];
            const uint32_t h3 = sPAH[pr1 + gp + 4];
            #pragma unroll
            for (int nt = 0; nt < 4; ++nt) {
                const int nl = wnl + nt * 8 + gid;
                mma_bf16(a2[nt], h0, h1, h2, h3, rwH[nl * 36 + gp], rwH[nl * 36 + gp + 4]);
            }
        }
        __syncthreads();

        if (c + 2 < 4) {
            const uint32_t hB = smem_u32(rwBuf[c & 1]);
            #pragma unroll
            for (int it = 0; it < 2; ++it) {
                const int idx = it * 256 + t;
                const int n  = idx >> 3;
                const int q4 = (idx & 7) * 4;
                cp_async16(hB + (uint32_t)(n * 144 + q4 * 4), g_rwbHi + ((c + 2) * 64 + n) * 32 + q4);
            }
            CP_COMMIT();
        }

        #pragma unroll
        for (int nt = 0; nt < 4; ++nt) {
            const int col = c * 64 + wnl + nt * 8 + 2 * tid4;
            const float aw0 = sAW[col], aw1v = sAW[col + 1];
            const float2 bw0 = *(const float2*)(bwr0 + col);
            const float2 bw1 = *(const float2*)(bwr1 + col);
            const uint32_t u0 = pkbf2(tanh_fast(a2[nt][0] + aw0 + bw0.x),
                                      tanh_fast(a2[nt][1] + aw1v + bw0.y));
            const uint32_t u1 = pkbf2(tanh_fast(a2[nt][2] + aw0 + bw1.x),
                                      tanh_fast(a2[nt][3] + aw1v + bw1.y));
            tvu[(tvb0 + col) >> 1] = u0;
            tvu[(tvb1 + col) >> 1] = u1;
            sAhi[row0 * 132 + (col >> 1)] = u0;
            sAhi[row1 * 132 + (col >> 1)] = u1;
        }
    }
    __syncthreads();   // sAhi complete; RA free

    // w1 chunk 0 fill ([32][132] u32 in RA, single buffer)
    {
        const uint32_t wB = smem_u32(sRA);
        #pragma unroll
        for (int it = 0; it < 4; ++it) {
            const int idx = it * 256 + t;       // 1024 uint4
            const int n  = idx >> 5;
            const int q4 = (idx & 31) * 4;
            cp_async16(wB + (uint32_t)(n * 528 + q4 * 4), g_w1bT + n * 128 + q4);
        }
        CP_COMMIT();
    }

    // ---- GEMM3: 8 n-chunks of 32 cols, A = bf16-hi ----
    const int ar0 = (wm + gid) * 132;
    const int ar1 = (wm + gid + 8) * 132;
    const uint32_t* wb = (const uint32_t*)sRA;
    float p0 = 0.0f, p1 = 0.0f;

    for (int c = 0; c < 8; ++c) {
        CP_WAIT0();
        __syncthreads();

        float a3[2][4];
        #pragma unroll
        for (int nt = 0; nt < 2; ++nt)
            #pragma unroll
            for (int e = 0; e < 4; ++e) a3[nt][e] = 0.0f;

        #pragma unroll 4
        for (int ks = 0; ks < 16; ++ks) {
            const int gp = ks * 8 + tid4;
            const uint32_t h0 = sAhi[ar0 + gp];
            const uint32_t h1 = sAhi[ar1 + gp];
            const uint32_t h2 = sAhi[ar0 + gp + 4];
            const uint32_t h3 = sAhi[ar1 + gp + 4];
            #pragma unroll
            for (int nt = 0; nt < 2; ++nt) {
                const int nl = wn2 + nt * 8 + gid;
                mma_bf16(a3[nt], h0, h1, h2, h3, wb[nl * 132 + gp], wb[nl * 132 + gp + 4]);
            }
        }
        __syncthreads();

        if (c < 7) {
            const uint32_t wB = smem_u32(sRA);
            #pragma unroll
            for (int it = 0; it < 4; ++it) {
                const int idx = it * 256 + t;
                const int n  = idx >> 5;
                const int q4 = (idx & 31) * 4;
                cp_async16(wB + (uint32_t)(n * 528 + q4 * 4),
                           g_w1bT + (size_t)((c + 1) * 32 + n) * 128 + q4);
            }
            CP_COMMIT();
        }

        #pragma unroll
        for (int nt = 0; nt < 2; ++nt) {
            const int col = c * 32 + wn2 + nt * 8 + 2 * tid4;
            p0 = fmaf(tanh_fast(a3[nt][0] + sb1[col]),     sw2[col],     p0);
            p0 = fmaf(tanh_fast(a3[nt][1] + sb1[col + 1]), sw2[col + 1], p0);
            p1 = fmaf(tanh_fast(a3[nt][2] + sb1[col]),     sw2[col],     p1);
            p1 = fmaf(tanh_fast(a3[nt][3] + sb1[col + 1]), sw2[col + 1], p1);
        }
    }

    // ---- reduce att partial sums ----
    p0 += __shfl_xor_sync(0xffffffffu, p0, 1);
    p0 += __shfl_xor_sync(0xffffffffu, p0, 2);
    p1 += __shfl_xor_sync(0xffffffffu, p1, 1);
    p1 += __shfl_xor_sync(0xffffffffu, p1, 2);

    if (wid < 4) {
        if (tid4 == 0) { sred[wm + gid] = p0; sred[wm + gid + 8] = p1; }
    }
    __syncthreads();
    if (wid >= 4) {
        if (tid4 == 0) { sred[wm + gid] += p0; sred[wm + gid + 8] += p1; }
    }
    __syncthreads();
    if (t < 64)
        g_att[b * NN + i * VV + t] = sred[t] + att_b2[0];
}

__global__ __launch_bounds__(256) void kAtt(float* __restrict__ out_attn)
{
    const int b = blockIdx.x, t = threadIdx.x;
    __shared__ float red[8];
    float vals[16];
    float mx = -1e30f;
    #pragma unroll
    for (int it = 0; it < 16; ++it) {
        vals[it] = g_att[b * NN + it * 256 + t];
        mx = fmaxf(mx, vals[it]);
    }
    #pragma unroll
    for (int o = 16; o; o >>= 1) mx = fmaxf(mx, __shfl_xor_sync(0xffffffffu, mx, o));
    if ((t & 31) == 0) red[t >> 5] = mx;
    __syncthreads();
    float bm = red[0];
    #pragma unroll
    for (int w = 1; w < 8; ++w) bm = fmaxf(bm, red[w]);
    __syncthreads();
    float s = 0.0f;
    #pragma unroll
    for (int it = 0; it < 16; ++it) { vals[it] = expf(vals[it] - bm); s += vals[it]; }
    #pragma unroll
    for (int o = 16; o; o >>= 1) s += __shfl_xor_sync(0xffffffffu, s, o);
    if ((t & 31) == 0) red[t >> 5] = s;
    __syncthreads();
    float bs = 0.0f;
    #pragma unroll
    for (int w = 0; w < 8; ++w) bs += red[w];
    const float inv = 1.0f / bs;
    #pragma unroll
    for (int it = 0; it < 16; ++it)
        out_attn[b * NN + it * 256 + t] = vals[it] * inv;
    g_fuse[b * DD + t] = 0.0f;
}

__global__ __launch_bounds__(256) void kFuse(const float* __restrict__ attn)
{
    const int b = blockIdx.x >> 6, ch = blockIdx.x & 63, t = threadIdx.x;
    __shared__ float sa[64];
    const int n0 = ch * 64;
    if (t < 64) sa[t] = attn[b * NN + n0 + t];
    __syncthreads();

    const __nv_bfloat16* tvp = g_tvh + ((size_t)(b * NN + n0)) * DD + t;
    float a0 = 0, a1 = 0, a2 = 0, a3 = 0, a4 = 0, a5 = 0, a6 = 0, a7 = 0;
    #pragma unroll
    for (int n = 0; n < 64; n += 8) {
        a0 = fmaf(sa[n + 0], __bfloat162float(tvp[(size_t)(n + 0) * DD]), a0);
        a1 = fmaf(sa[n + 1], __bfloat162float(tvp[(size_t)(n + 1) * DD]), a1);
        a2 = fmaf(sa[n + 2], __bfloat162float(tvp[(size_t)(n + 2) * DD]), a2);
        a3 = fmaf(sa[n + 3], __bfloat162float(tvp[(size_t)(n + 3) * DD]), a3);
        a4 = fmaf(sa[n + 4], __bfloat162float(tvp[(size_t)(n + 4) * DD]), a4);
        a5 = fmaf(sa[n + 5], __bfloat162float(tvp[(size_t)(n + 5) * DD]), a5);
        a6 = fmaf(sa[n + 6], __bfloat162float(tvp[(size_t)(n + 6) * DD]), a6);
        a7 = fmaf(sa[n + 7], __bfloat162float(tvp[(size_t)(n + 7) * DD]), a7);
    }
    atomicAdd(&g_fuse[b * DD + t], ((a0 + a1) + (a2 + a3)) + ((a4 + a5) + (a6 + a7)));
}

__global__ __launch_bounds__(256) void kLogits(
    float* __restrict__ out, const float* __restrict__ ow, const float* __restrict__ ob)
{
    const int b = blockIdx.x, t = threadIdx.x;
    __shared__ float red[8];
    float v = g_fuse[b * DD + t] * ow[t];
    #pragma unroll
    for (int o = 16; o; o >>= 1) v += __shfl_xor_sync(0xffffffffu, v, o);
    if ((t & 31) == 0) red[t >> 5] = v;
    __syncthreads();
    if (t == 0) {
        float s = 0.0f;
        #pragma unroll
        for (int w = 0; w < 8; ++w) s += red[w];
        out[b] = s + ob[0];
    }
}

extern "C" void kernel_launch(void* const* d_in, const int* in_sizes, int n_in,
                              void* d_out, int out_size)
{
    const int*   head = (const int*)d_in[0];
    const int*   tail = (const int*)d_in[1];
    const float* emb  = (const float*)d_in[2];
    const float* rela = (const float*)d_in[3];
    const float* fc_w = (const float*)d_in[4];
    const float* fc_b = (const float*)d_in[5];
    const float* aw1  = (const float*)d_in[6];
    const float* ab1  = (const float*)d_in[7];
    const float* aw2  = (const float*)d_in[8];
    const float* ab2  = (const float*)d_in[9];
    const float* ow   = (const float*)d_in[10];
    const float* ob   = (const float*)d_in[11];

    float* out        = (float*)d_out;
    float* out_logits = out;
    float* out_attn   = out + BB;
    float* out_ns     = out + BB + BB * NN;

    cudaFuncSetAttribute(kMain, cudaFuncAttributeMaxDynamicSharedMemorySize, SMEM_M_BYTES);

    kPre   <<<132,   256>>>(head, tail, emb, rela, fc_w, fc_b);
    kW1T   <<<128,   256>>>(aw1);
    kRWT   <<<32,    256>>>();
    kMain  <<<BB*WW, 256, SMEM_M_BYTES>>>(ab1, aw2, ab2, out_ns);
    kAtt   <<<BB,    256>>>(out_attn);
    kFuse  <<<BB*64, 256>>>(out_attn);
    kLogits<<<BB,    256>>>(out_logits, ow, ob);
}

// round 15
// speedup vs baseline: 1.1919x; 1.1919x over previous
#include <cuda_runtime.h>
#include <cuda_bf16.h>
#include <cstdint>
#include <cstddef>

#define BB   16
#define WW   64
#define VV   64
#define DD   256
#define RR   64
#define NN   (WW*VV)
#define PAD  68

typedef unsigned long long ull;

__device__ float g_A   [BB*WW*DD];
__device__ float g_BtT [BB*DD*VV];
__device__ float g_relaT[DD*RR];
__device__ float g_AW  [BB*WW*DD];
__device__ float g_BW  [BB*VV*DD];
__device__ float g_RW  [RR*DD];
__device__ uint32_t g_w1bT [DD*DD/2];      // w1^T bf16 pairs, perm8 within 8-groups
__device__ uint32_t g_rwbHi[DD*RR/2];      // RW^T bf16 pairs, perm8
__device__ __nv_bfloat16 g_tvh[(size_t)BB*NN*DD];
__device__ float g_att [BB*NN];
__device__ float g_fuse[BB*DD];

__device__ __forceinline__ float tanh_fast(float x) {
    float y; asm("tanh.approx.f32 %0, %1;" : "=f"(y) : "f"(x)); return y;
}
__device__ __forceinline__ ull fma2(ull a, ull b, ull c) {
    ull d; asm("fma.rn.f32x2 %0, %1, %2, %3;" : "=l"(d) : "l"(a), "l"(b), "l"(c)); return d;
}
__device__ __forceinline__ ull pack2(float x) {
    ull r; asm("mov.b64 %0, {%1, %1};" : "=l"(r) : "f"(x)); return r;
}
__device__ __forceinline__ float2 unpack2(ull v) {
    float2 f; asm("mov.b64 {%0, %1}, %2;" : "=f"(f.x), "=f"(f.y) : "l"(v)); return f;
}
__device__ __forceinline__ uint32_t smem_u32(const void* p) {
    uint32_t a;
    asm("{ .reg .u64 tmp; cvta.to.shared.u64 tmp, %1; cvt.u32.u64 %0, tmp; }" : "=r"(a) : "l"(p));
    return a;
}
__device__ __forceinline__ void cp_async16(uint32_t daddr, const void* src) {
    asm volatile("cp.async.cg.shared.global [%0], [%1], 16;" :: "r"(daddr), "l"(src) : "memory");
}
#define CP_COMMIT() asm volatile("cp.async.commit_group;" ::: "memory")
#define CP_WAIT0()  asm volatile("cp.async.wait_group 0;" ::: "memory")
#define CP_WAIT1()  asm volatile("cp.async.wait_group 1;" ::: "memory")

__device__ __forceinline__ void mma_bf16(float c[4],
    uint32_t a0, uint32_t a1, uint32_t a2, uint32_t a3, uint32_t b0, uint32_t b1)
{
    asm volatile(
        "mma.sync.aligned.m16n8k16.row.col.f32.bf16.bf16.f32 "
        "{%0,%1,%2,%3}, {%4,%5,%6,%7}, {%8,%9}, {%0,%1,%2,%3};"
        : "+f"(c[0]), "+f"(c[1]), "+f"(c[2]), "+f"(c[3])
        : "r"(a0), "r"(a1), "r"(a2), "r"(a3), "r"(b0), "r"(b1));
}
__device__ __forceinline__ uint32_t pkbf2(float a, float b) {
    return (uint32_t)__bfloat16_as_ushort(__float2bfloat16_rn(a))
         | ((uint32_t)__bfloat16_as_ushort(__float2bfloat16_rn(b)) << 16);
}
// pair-index permutation within groups of 8: old m -> (m&3)*2 + (m>>2)
__device__ __forceinline__ int perm8(int p) {
    return (p & ~7) | (((p & 3) << 1) | ((p >> 2) & 1));
}
__device__ __forceinline__ uint32_t lo32(ull v) { return (uint32_t)v; }
__device__ __forceinline__ uint32_t hi32(ull v) { return (uint32_t)(v >> 32); }

__global__ __launch_bounds__(256) void kW1T(const float* __restrict__ aw1)
{
    const int p = blockIdx.x, n = threadIdx.x;
    g_w1bT[n * 128 + perm8(p)] = pkbf2(aw1[(2 * p) * DD + n], aw1[(2 * p + 1) * DD + n]);
}

__global__ __launch_bounds__(256) void kRWT()
{
    const int p = blockIdx.x, n = threadIdx.x;
    g_rwbHi[n * 32 + perm8(p)] = pkbf2(g_RW[(2 * p) * DD + n], g_RW[(2 * p + 1) * DD + n]);
}

__global__ __launch_bounds__(256) void kPre(
    const int* __restrict__ head, const int* __restrict__ tail,
    const float* __restrict__ emb, const float* __restrict__ rela,
    const float* __restrict__ fc_w, const float* __restrict__ fc_b)
{
    __shared__ float sX[16][257];
    const int g = blockIdx.x, t = threadIdx.x;
    const int kind = (g < 64) ? 0 : (g < 128 ? 1 : 2);
    const int row0 = ((kind == 0) ? g : (kind == 1) ? (g - 64) : (g - 128)) * 16;

    #pragma unroll 4
    for (int rr = 0; rr < 16; ++rr) {
        const int row = row0 + rr;
        float v;
        if (kind == 0)      v = emb[(size_t)head[row] * DD + t];
        else if (kind == 1) v = emb[(size_t)tail[row] * DD + t];
        else                v = rela[row * DD + t];
        sX[rr][t] = v;
        if (kind == 0) g_A[row * DD + t] = v;
    }
    __syncthreads();

    const float* Wp = fc_w + (size_t)kind * DD * DD;
    float acc[16];
    #pragma unroll
    for (int r = 0; r < 16; ++r) acc[r] = (kind == 0) ? fc_b[t] : 0.0f;
    #pragma unroll 4
    for (int k = 0; k < DD; ++k) {
        const float wv = Wp[k * DD + t];
        #pragma unroll
        for (int r = 0; r < 16; ++r) acc[r] = fmaf(sX[r][k], wv, acc[r]);
    }
    float* dst = (kind == 0) ? g_AW : (kind == 1) ? g_BW : g_RW;
    #pragma unroll
    for (int r = 0; r < 16; ++r) dst[(row0 + r) * DD + t] = acc[r];

    if (kind != 0) {
        float* dstT = (kind == 1)
            ? (g_BtT + (size_t)(row0 >> 6) * DD * VV + (row0 & 63))
            : (g_relaT + row0);
        #pragma unroll
        for (int it = 0; it < 4; ++it) {
            const int f = it * 256 + t;
            const int d = f >> 2, q = f & 3;
            float4 v;
            v.x = sX[q * 4 + 0][d]; v.y = sX[q * 4 + 1][d];
            v.z = sX[q * 4 + 2][d]; v.w = sX[q * 4 + 3][d];
            *(float4*)&dstT[d * 64 + q * 4] = v;
        }
    }
}

// ---------------------------------------------------------------------------
// kMain: R13 structure, pair-interleaved mma operands (LDS.64 fragments).
// smem 107776 B -> 2 CTAs/SM.
// ---------------------------------------------------------------------------
#define SM_RA    0
#define SM_SP    10240
#define SM_PAH   14592
#define SM_AH    17152
#define SM_SA    25856
#define SM_SAW   26112
#define SM_SB1   26368
#define SM_SW2   26624
#define SM_SRED  26880
#define SMEM_M_FLOATS 26944
#define SMEM_M_BYTES  (SMEM_M_FLOATS * 4)

__global__ __launch_bounds__(256, 2) void kMain(
    const float* __restrict__ att_b1, const float* __restrict__ att_w2,
    const float* __restrict__ att_b2, float* __restrict__ out_ns)
{
    const int t  = threadIdx.x;
    const int b  = blockIdx.x >> 6;
    const int i  = blockIdx.x & 63;
    const int lane = t & 31, wid = t >> 5;
    const int tx = t & 15, ty = t >> 4;
    const int j0g = ty * 4, r0 = tx * 4;
    const int gid = lane >> 2, tid4 = lane & 3;
    const int wm  = (wid & 3) * 16;
    const int wnl = (wid >> 2) * 32;

    extern __shared__ float sm[];
    float*    sRA  = sm + SM_RA;
    float*    sP   = sm + SM_SP;
    uint32_t* sPAH = (uint32_t*)(sm + SM_PAH);   // [64][40] u32, perm8 pairs
    uint32_t* sAhi = (uint32_t*)(sm + SM_AH);    // [64][136] u32, perm8 pairs
    float*    sA   = sm + SM_SA;
    float*    sAW  = sm + SM_SAW;
    float*    sb1  = sm + SM_SB1;
    float*    sw2  = sm + SM_SW2;
    float*    sred = sm + SM_SRED;

    const int rowA = b * WW + i;
    sA [t] = g_A [rowA * DD + t];
    sAW[t] = g_AW[rowA * DD + t];
    sb1[t] = att_b1[t];
    sw2[t] = att_w2[t];
    __syncthreads();

    // ---- GEMM1: scalar fp32, 8 k-chunks of 32d, pipelined fills ----
    const float* btT = g_BtT + (size_t)b * DD * VV;
    float* hb[2] = { sRA, sRA + 4352 };
    float* rb[2] = { sRA + 2176, sRA + 6528 };
    const int fd = t >> 4;
    const int fc = (t & 15) * 4;

    float4 hpre[2];
    #pragma unroll
    for (int it = 0; it < 2; ++it) {
        const int d = it * 16 + fd;
        float4 v = *(const float4*)(btT + d * 64 + fc);
        const float sa = sA[d];
        v.x *= sa; v.y *= sa; v.z *= sa; v.w *= sa;
        *(float4*)&hb[0][d * PAD + fc] = v;
    }
    #pragma unroll
    for (int it = 0; it < 2; ++it)
        hpre[it] = *(const float4*)(btT + (32 + it * 16 + fd) * 64 + fc);
    #pragma unroll
    for (int s = 0; s < 2; ++s) {
        const uint32_t rB = smem_u32(rb[s]);
        #pragma unroll
        for (int it = 0; it < 2; ++it) {
            const int d = it * 16 + fd;
            cp_async16(rB + (uint32_t)(d * PAD + fc) * 4, g_relaT + (s * 32 + d) * 64 + fc);
        }
        CP_COMMIT();
    }

    ull c1[4][2];
    #pragma unroll
    for (int u = 0; u < 4; ++u) { c1[u][0] = 0ull; c1[u][1] = 0ull; }

    for (int kc = 0; kc < 8; ++kc) {
        if (kc < 7) { CP_WAIT1(); } else { CP_WAIT0(); }
        __syncthreads();
        const float* hh = hb[kc & 1];
        const float* rr = rb[kc & 1];
        #pragma unroll 4
        for (int d = 0; d < 32; ++d) {
            const float4 h4 = *(const float4*)&hh[d * PAD + j0g];
            const ulonglong2 r2 = *(const ulonglong2*)&rr[d * PAD + r0];
            const ull hp[4] = {pack2(h4.x), pack2(h4.y), pack2(h4.z), pack2(h4.w)};
            #pragma unroll
            for (int u = 0; u < 4; ++u) {
                c1[u][0] = fma2(hp[u], r2.x, c1[u][0]);
                c1[u][1] = fma2(hp[u], r2.y, c1[u][1]);
            }
        }
        __syncthreads();
        if (kc < 7) {
            float* hd = hb[(kc + 1) & 1];
            #pragma unroll
            for (int it = 0; it < 2; ++it) {
                const int d = it * 16 + fd;
                const float sa = sA[(kc + 1) * 32 + d];
                float4 v = hpre[it];
                v.x *= sa; v.y *= sa; v.z *= sa; v.w *= sa;
                *(float4*)&hd[d * PAD + fc] = v;
            }
            if (kc < 6) {
                #pragma unroll
                for (int it = 0; it < 2; ++it)
                    hpre[it] = *(const float4*)(btT + ((kc + 2) * 32 + it * 16 + fd) * 64 + fc);
                const uint32_t rB = smem_u32(rb[kc & 1]);
                #pragma unroll
                for (int it = 0; it < 2; ++it) {
                    const int d = it * 16 + fd;
                    cp_async16(rB + (uint32_t)(d * PAD + fc) * 4,
                               g_relaT + ((kc + 2) * 32 + d) * 64 + fc);
                }
                CP_COMMIT();
            }
        }
    }
    #pragma unroll
    for (int u = 0; u < 4; ++u) {
        const float2 lo = unpack2(c1[u][0]);
        const float2 hi = unpack2(c1[u][1]);
        *(float4*)&sP[(j0g + u) * PAD + r0] = make_float4(lo.x, lo.y, hi.x, hi.y);
    }
    __syncthreads();

    // RW full image ([256][40] u32, perm8 rows) -> RA; overlaps softmax
    {
        const uint32_t hB = smem_u32(sRA);
        #pragma unroll
        for (int it = 0; it < 8; ++it) {
            const int idx = it * 256 + t;   // 2048 uint4
            const int n  = idx >> 3;
            const int q4 = (idx & 7) * 4;
            cp_async16(hB + (uint32_t)(n * 160 + q4 * 4), g_rwbHi + n * 32 + q4);
        }
        CP_COMMIT();
    }

    // ---- softmax + permuted P pair pack ----
    {
        const int j = t >> 2, q = t & 3;
        const float nul = sP[j * PAD + 63];
        float v[16];
        float mx = -1e30f;
        #pragma unroll
        for (int m = 0; m < 16; ++m) {
            float s = sP[j * PAD + q * 16 + m];
            s = (s <= nul) ? -1e10f : s;
            v[m] = s;
            mx = fmaxf(mx, s);
        }
        mx = fmaxf(mx, __shfl_xor_sync(0xffffffffu, mx, 1));
        mx = fmaxf(mx, __shfl_xor_sync(0xffffffffu, mx, 2));
        float se = 0.0f;
        #pragma unroll
        for (int m = 0; m < 16; ++m) { v[m] = expf(v[m] - mx); se += v[m]; }
        se += __shfl_xor_sync(0xffffffffu, se, 1);
        se += __shfl_xor_sync(0xffffffffu, se, 2);
        const float inv = 1.0f / se;
        #pragma unroll
        for (int m = 0; m < 16; ++m) { v[m] *= inv; sP[j * PAD + q * 16 + m] = v[m]; }
        #pragma unroll
        for (int mm = 0; mm < 8; ++mm) {
            // pair index q*8+mm -> permuted slot q*8 + (mm&3)*2 + (mm>>2)
            const int slot = q * 8 + ((mm & 3) << 1) + (mm >> 2);
            sPAH[j * 40 + slot] = pkbf2(v[2 * mm], v[2 * mm + 1]);
        }
    }
    __syncthreads();

    const size_t ns_base = ((size_t)(b * NN + i * VV)) * RR;
    #pragma unroll
    for (int it = 0; it < 16; ++it) {
        const int l = it * 256 + t;
        out_ns[ns_base + (size_t)(l >> 6) * RR + (l & 63)] = sP[(l >> 6) * PAD + (l & 63)];
    }
    CP_WAIT0();
    __syncthreads();

    // ---- GEMM2: PV = P @ RW, bf16, 4 n-chunks, LDS.64 fragments ----
    const uint32_t* rwH = (const uint32_t*)sRA;
    const int pr0 = (wm + gid) * 40;
    const int pr1 = (wm + gid + 8) * 40;
    const int row0 = wm + gid, row1 = wm + gid + 8;
    const size_t tvb0 = ((size_t)(b * NN + i * VV + row0)) * DD;
    const size_t tvb1 = ((size_t)(b * NN + i * VV + row1)) * DD;
    const float* bwr0 = g_BW + (size_t)(b * VV + row0) * DD;
    const float* bwr1 = g_BW + (size_t)(b * VV + row1) * DD;
    uint32_t* tvu = (uint32_t*)g_tvh;

    for (int c = 0; c < 4; ++c) {
        float a2[4][4];
        #pragma unroll
        for (int nt = 0; nt < 4; ++nt)
            #pragma unroll
            for (int e = 0; e < 4; ++e) a2[nt][e] = 0.0f;

        #pragma unroll
        for (int ks = 0; ks < 4; ++ks) {
            const int np = ks * 8 + 2 * tid4;
            const ull A0 = *(const ull*)&sPAH[pr0 + np];   // (h0, h2)
            const ull A1 = *(const ull*)&sPAH[pr1 + np];   // (h1, h3)
            #pragma unroll
            for (int nt = 0; nt < 4; ++nt) {
                const int n = c * 64 + wnl + nt * 8 + gid;
                const ull B = *(const ull*)&rwH[n * 40 + np];
                mma_bf16(a2[nt], lo32(A0), lo32(A1), hi32(A0), hi32(A1), lo32(B), hi32(B));
            }
        }

        #pragma unroll
        for (int nt = 0; nt < 4; ++nt) {
            const int col = c * 64 + wnl + nt * 8 + 2 * tid4;
            const float aw0 = sAW[col], aw1v = sAW[col + 1];
            const float2 bw0 = *(const float2*)(bwr0 + col);
            const float2 bw1 = *(const float2*)(bwr1 + col);
            const uint32_t u0 = pkbf2(tanh_fast(a2[nt][0] + aw0 + bw0.x),
                                      tanh_fast(a2[nt][1] + aw1v + bw0.y));
            const uint32_t u1 = pkbf2(tanh_fast(a2[nt][2] + aw0 + bw1.x),
                                      tanh_fast(a2[nt][3] + aw1v + bw1.y));
            tvu[(tvb0 + col) >> 1] = u0;
            tvu[(tvb1 + col) >> 1] = u1;
            const int p = col >> 1;
            sAhi[row0 * 136 + perm8(p)] = u0;
            sAhi[row1 * 136 + perm8(p)] = u1;
        }
    }
    __syncthreads();   // sAhi complete; RA free

    // w1 chunk 0 fill ([64][136] u32 in RA)
    {
        const uint32_t wB = smem_u32(sRA);
        #pragma unroll
        for (int it = 0; it < 8; ++it) {
            const int idx = it * 256 + t;   // 2048 uint4
            const int n  = idx >> 5;
            const int q4 = (idx & 31) * 4;
            cp_async16(wB + (uint32_t)(n * 544 + q4 * 4), g_w1bT + n * 128 + q4);
        }
        CP_COMMIT();
    }

    // ---- GEMM3: 4 n-chunks of 64 cols, A = bf16-hi, LDS.64 fragments ----
    const int ar0 = (wm + gid) * 136;
    const int ar1 = (wm + gid + 8) * 136;
    const uint32_t* wb = (const uint32_t*)sRA;
    float p0 = 0.0f, p1 = 0.0f;

    for (int c = 0; c < 4; ++c) {
        CP_WAIT0();
        __syncthreads();

        float a3[4][4];
        #pragma unroll
        for (int nt = 0; nt < 4; ++nt)
            #pragma unroll
            for (int e = 0; e < 4; ++e) a3[nt][e] = 0.0f;

        #pragma unroll 4
        for (int ks = 0; ks < 16; ++ks) {
            const int np = ks * 8 + 2 * tid4;
            const ull A0 = *(const ull*)&sAhi[ar0 + np];
            const ull A1 = *(const ull*)&sAhi[ar1 + np];
            #pragma unroll
            for (int nt = 0; nt < 4; ++nt) {
                const int nl = wnl + nt * 8 + gid;
                const ull B = *(const ull*)&wb[nl * 136 + np];
                mma_bf16(a3[nt], lo32(A0), lo32(A1), hi32(A0), hi32(A1), lo32(B), hi32(B));
            }
        }
        __syncthreads();

        if (c < 3) {
            const uint32_t wB = smem_u32(sRA);
            #pragma unroll
            for (int it = 0; it < 8; ++it) {
                const int idx = it * 256 + t;
                const int n  = idx >> 5;
                const int q4 = (idx & 31) * 4;
                cp_async16(wB + (uint32_t)(n * 544 + q4 * 4),
                           g_w1bT + (size_t)((c + 1) * 64 + n) * 128 + q4);
            }
            CP_COMMIT();
        }

        #pragma unroll
        for (int nt = 0; nt < 4; ++nt) {
            const int col = c * 64 + wnl + nt * 8 + 2 * tid4;
            p0 = fmaf(tanh_fast(a3[nt][0] + sb1[col]),     sw2[col],     p0);
            p0 = fmaf(tanh_fast(a3[nt][1] + sb1[col + 1]), sw2[col + 1], p0);
            p1 = fmaf(tanh_fast(a3[nt][2] + sb1[col]),     sw2[col],     p1);
            p1 = fmaf(tanh_fast(a3[nt][3] + sb1[col + 1]), sw2[col + 1], p1);
        }
    }

    // ---- reduce att partial sums ----
    p0 += __shfl_xor_sync(0xffffffffu, p0, 1);
    p0 += __shfl_xor_sync(0xffffffffu, p0, 2);
    p1 += __shfl_xor_sync(0xffffffffu, p1, 1);
    p1 += __shfl_xor_sync(0xffffffffu, p1, 2);

    if (wid < 4) {
        if (tid4 == 0) { sred[wm + gid] = p0; sred[wm + gid + 8] = p1; }
    }
    __syncthreads();
    if (wid >= 4) {
        if (tid4 == 0) { sred[wm + gid] += p0; sred[wm + gid + 8] += p1; }
    }
    __syncthreads();
    if (t < 64)
        g_att[b * NN + i * VV + t] = sred[t] + att_b2[0];
}

__global__ __launch_bounds__(256) void kAtt(float* __restrict__ out_attn)
{
    const int b = blockIdx.x, t = threadIdx.x;
    __shared__ float red[8];
    float vals[16];
    float mx = -1e30f;
    #pragma unroll
    for (int it = 0; it < 16; ++it) {
        vals[it] = g_att[b * NN + it * 256 + t];
        mx = fmaxf(mx, vals[it]);
    }
    #pragma unroll
    for (int o = 16; o; o >>= 1) mx = fmaxf(mx, __shfl_xor_sync(0xffffffffu, mx, o));
    if ((t & 31) == 0) red[t >> 5] = mx;
    __syncthreads();
    float bm = red[0];
    #pragma unroll
    for (int w = 1; w < 8; ++w) bm = fmaxf(bm, red[w]);
    __syncthreads();
    float s = 0.0f;
    #pragma unroll
    for (int it = 0; it < 16; ++it) { vals[it] = expf(vals[it] - bm); s += vals[it]; }
    #pragma unroll
    for (int o = 16; o; o >>= 1) s += __shfl_xor_sync(0xffffffffu, s, o);
    if ((t & 31) == 0) red[t >> 5] = s;
    __syncthreads();
    float bs = 0.0f;
    #pragma unroll
    for (int w = 0; w < 8; ++w) bs += red[w];
    const float inv = 1.0f / bs;
    #pragma unroll
    for (int it = 0; it < 16; ++it)
        out_attn[b * NN + it * 256 + t] = vals[it] * inv;
    g_fuse[b * DD + t] = 0.0f;
}

__global__ __launch_bounds__(256) void kFuse(const float* __restrict__ attn)
{
    const int b = blockIdx.x >> 6, ch = blockIdx.x & 63, t = threadIdx.x;
    __shared__ float sa[64];
    const int n0 = ch * 64;
    if (t < 64) sa[t] = attn[b * NN + n0 + t];
    __syncthreads();

    const __nv_bfloat16* tvp = g_tvh + ((size_t)(b * NN + n0)) * DD + t;
    float a0 = 0, a1 = 0, a2 = 0, a3 = 0, a4 = 0, a5 = 0, a6 = 0, a7 = 0;
    #pragma unroll
    for (int n = 0; n < 64; n += 8) {
        a0 = fmaf(sa[n + 0], __bfloat162float(tvp[(size_t)(n + 0) * DD]), a0);
        a1 = fmaf(sa[n + 1], __bfloat162float(tvp[(size_t)(n + 1) * DD]), a1);
        a2 = fmaf(sa[n + 2], __bfloat162float(tvp[(size_t)(n + 2) * DD]), a2);
        a3 = fmaf(sa[n + 3], __bfloat162float(tvp[(size_t)(n + 3) * DD]), a3);
        a4 = fmaf(sa[n + 4], __bfloat162float(tvp[(size_t)(n + 4) * DD]), a4);
        a5 = fmaf(sa[n + 5], __bfloat162float(tvp[(size_t)(n + 5) * DD]), a5);
        a6 = fmaf(sa[n + 6], __bfloat162float(tvp[(size_t)(n + 6) * DD]), a6);
        a7 = fmaf(sa[n + 7], __bfloat162float(tvp[(size_t)(n + 7) * DD]), a7);
    }
    atomicAdd(&g_fuse[b * DD + t], ((a0 + a1) + (a2 + a3)) + ((a4 + a5) + (a6 + a7)));
}

__global__ __launch_bounds__(256) void kLogits(
    float* __restrict__ out, const float* __restrict__ ow, const float* __restrict__ ob)
{
    const int b = blockIdx.x, t = threadIdx.x;
    __shared__ float red[8];
    float v = g_fuse[b * DD + t] * ow[t];
    #pragma unroll
    for (int o = 16; o; o >>= 1) v += __shfl_xor_sync(0xffffffffu, v, o);
    if ((t & 31) == 0) red[t >> 5] = v;
    __syncthreads();
    if (t == 0) {
        float s = 0.0f;
        #pragma unroll
        for (int w = 0; w < 8; ++w) s += red[w];
        out[b] = s + ob[0];
    }
}

extern "C" void kernel_launch(void* const* d_in, const int* in_sizes, int n_in,
                              void* d_out, int out_size)
{
    const int*   head = (const int*)d_in[0];
    const int*   tail = (const int*)d_in[1];
    const float* emb  = (const float*)d_in[2];
    const float* rela = (const float*)d_in[3];
    const float* fc_w = (const float*)d_in[4];
    const float* fc_b = (const float*)d_in[5];
    const float* aw1  = (const float*)d_in[6];
    const float* ab1  = (const float*)d_in[7];
    const float* aw2  = (const float*)d_in[8];
    const float* ab2  = (const float*)d_in[9];
    const float* ow   = (const float*)d_in[10];
    const float* ob   = (const float*)d_in[11];

    float* out        = (float*)d_out;
    float* out_logits = out;
    float* out_attn   = out + BB;
    float* out_ns     = out + BB + BB * NN;

    cudaFuncSetAttribute(kMain, cudaFuncAttributeMaxDynamicSharedMemorySize, SMEM_M_BYTES);

    kPre   <<<132,   256>>>(head, tail, emb, rela, fc_w, fc_b);
    kW1T   <<<128,   256>>>(aw1);
    kRWT   <<<32,    256>>>();
    kMain  <<<BB*WW, 256, SMEM_M_BYTES>>>(ab1, aw2, ab2, out_ns);
    kAtt   <<<BB,    256>>>(out_attn);
    kFuse  <<<BB*64, 256>>>(out_attn);
    kLogits<<<BB,    256>>>(out_logits, ow, ob);
}

// round 17
// speedup vs baseline: 1.2717x; 1.0670x over previous
#include <cuda_runtime.h>
#include <cuda_bf16.h>
#include <cstdint>
#include <cstddef>

#define BB   16
#define WW   64
#define VV   64
#define DD   256
#define RR   64
#define NN   (WW*VV)
#define PAD  68

typedef unsigned long long ull;

__device__ float g_A   [BB*WW*DD];
__device__ float g_BtT [BB*DD*VV];
__device__ float g_relaT[DD*RR];
__device__ float g_AW  [BB*WW*DD];
__device__ float g_BW  [BB*VV*DD];
__device__ float g_RW  [RR*DD];
__device__ uint32_t g_w1bT [DD*DD/2];      // w1^T bf16 pairs, perm8
__device__ uint32_t g_rwbHi[DD*RR/2];      // RW^T bf16 pairs, perm8
__device__ float g_att  [BB*NN];
__device__ float g_fuseN[BB*DD];           // unnormalized fuse accumulators
__device__ float g_Z    [BB];              // exp-sum accumulators

__device__ __forceinline__ float tanh_fast(float x) {
    float y; asm("tanh.approx.f32 %0, %1;" : "=f"(y) : "f"(x)); return y;
}
__device__ __forceinline__ ull fma2(ull a, ull b, ull c) {
    ull d; asm("fma.rn.f32x2 %0, %1, %2, %3;" : "=l"(d) : "l"(a), "l"(b), "l"(c)); return d;
}
__device__ __forceinline__ ull pack2(float x) {
    ull r; asm("mov.b64 %0, {%1, %1};" : "=l"(r) : "f"(x)); return r;
}
__device__ __forceinline__ float2 unpack2(ull v) {
    float2 f; asm("mov.b64 {%0, %1}, %2;" : "=f"(f.x), "=f"(f.y) : "l"(v)); return f;
}
__device__ __forceinline__ uint32_t smem_u32(const void* p) {
    uint32_t a;
    asm("{ .reg .u64 tmp; cvta.to.shared.u64 tmp, %1; cvt.u32.u64 %0, tmp; }" : "=r"(a) : "l"(p));
    return a;
}
__device__ __forceinline__ void cp_async16(uint32_t daddr, const void* src) {
    asm volatile("cp.async.cg.shared.global [%0], [%1], 16;" :: "r"(daddr), "l"(src) : "memory");
}
#define CP_COMMIT() asm volatile("cp.async.commit_group;" ::: "memory")
#define CP_WAIT0()  asm volatile("cp.async.wait_group 0;" ::: "memory")
#define CP_WAIT1()  asm volatile("cp.async.wait_group 1;" ::: "memory")

__device__ __forceinline__ void mma_bf16(float c[4],
    uint32_t a0, uint32_t a1, uint32_t a2, uint32_t a3, uint32_t b0, uint32_t b1)
{
    asm volatile(
        "mma.sync.aligned.m16n8k16.row.col.f32.bf16.bf16.f32 "
        "{%0,%1,%2,%3}, {%4,%5,%6,%7}, {%8,%9}, {%0,%1,%2,%3};"
        : "+f"(c[0]), "+f"(c[1]), "+f"(c[2]), "+f"(c[3])
        : "r"(a0), "r"(a1), "r"(a2), "r"(a3), "r"(b0), "r"(b1));
}
__device__ __forceinline__ uint32_t pkbf2(float a, float b) {
    return (uint32_t)__bfloat16_as_ushort(__float2bfloat16_rn(a))
         | ((uint32_t)__bfloat16_as_ushort(__float2bfloat16_rn(b)) << 16);
}
__device__ __forceinline__ int perm8(int p) {
    return (p & ~7) | (((p & 3) << 1) | ((p >> 2) & 1));
}
__device__ __forceinline__ uint32_t lo32(ull v) { return (uint32_t)v; }
__device__ __forceinline__ uint32_t hi32(ull v) { return (uint32_t)(v >> 32); }
__device__ __forceinline__ float bf16bits_f(uint32_t h) {
    return __uint_as_float(h << 16);
}

__global__ __launch_bounds__(256) void kW1T(const float* __restrict__ aw1)
{
    const int p = blockIdx.x, n = threadIdx.x;
    g_w1bT[n * 128 + perm8(p)] = pkbf2(aw1[(2 * p) * DD + n], aw1[(2 * p + 1) * DD + n]);
}

__global__ __launch_bounds__(256) void kRWT()
{
    const int p = blockIdx.x, n = threadIdx.x;
    g_rwbHi[n * 32 + perm8(p)] = pkbf2(g_RW[(2 * p) * DD + n], g_RW[(2 * p + 1) * DD + n]);
    // zero fuse accumulators (runs before kMain every launch)
    const int idx = blockIdx.x * 256 + threadIdx.x;
    if (idx < BB * DD) g_fuseN[idx] = 0.0f;
    if (idx < BB)      g_Z[idx]     = 0.0f;
}

__global__ __launch_bounds__(256) void kPre(
    const int* __restrict__ head, const int* __restrict__ tail,
    const float* __restrict__ emb, const float* __restrict__ rela,
    const float* __restrict__ fc_w, const float* __restrict__ fc_b)
{
    __shared__ float sX[16][257];
    const int g = blockIdx.x, t = threadIdx.x;
    const int kind = (g < 64) ? 0 : (g < 128 ? 1 : 2);
    const int row0 = ((kind == 0) ? g : (kind == 1) ? (g - 64) : (g - 128)) * 16;

    #pragma unroll 4
    for (int rr = 0; rr < 16; ++rr) {
        const int row = row0 + rr;
        float v;
        if (kind == 0)      v = emb[(size_t)head[row] * DD + t];
        else if (kind == 1) v = emb[(size_t)tail[row] * DD + t];
        else                v = rela[row * DD + t];
        sX[rr][t] = v;
        if (kind == 0) g_A[row * DD + t] = v;
    }
    __syncthreads();

    const float* Wp = fc_w + (size_t)kind * DD * DD;
    float acc[16];
    #pragma unroll
    for (int r = 0; r < 16; ++r) acc[r] = (kind == 0) ? fc_b[t] : 0.0f;
    #pragma unroll 4
    for (int k = 0; k < DD; ++k) {
        const float wv = Wp[k * DD + t];
        #pragma unroll
        for (int r = 0; r < 16; ++r) acc[r] = fmaf(sX[r][k], wv, acc[r]);
    }
    float* dst = (kind == 0) ? g_AW : (kind == 1) ? g_BW : g_RW;
    #pragma unroll
    for (int r = 0; r < 16; ++r) dst[(row0 + r) * DD + t] = acc[r];

    if (kind != 0) {
        float* dstT = (kind == 1)
            ? (g_BtT + (size_t)(row0 >> 6) * DD * VV + (row0 & 63))
            : (g_relaT + row0);
        #pragma unroll
        for (int it = 0; it < 4; ++it) {
            const int f = it * 256 + t;
            const int d = f >> 2, q = f & 3;
            float4 v;
            v.x = sX[q * 4 + 0][d]; v.y = sX[q * 4 + 1][d];
            v.z = sX[q * 4 + 2][d]; v.w = sX[q * 4 + 3][d];
            *(float4*)&dstT[d * 64 + q * 4] = v;
        }
    }
}

// ---------------------------------------------------------------------------
// kMain: R15 structure + in-kernel fuse accumulation (no g_tvh, no kFuse).
// smem 107776 B -> 2 CTAs/SM.
// ---------------------------------------------------------------------------
#define SM_RA    0
#define SM_SP    10240
#define SM_PAH   14592
#define SM_AH    17152
#define SM_SA    25856
#define SM_SAW   26112
#define SM_SB1   26368
#define SM_SW2   26624
#define SM_SRED  26880
#define SMEM_M_FLOATS 26944
#define SMEM_M_BYTES  (SMEM_M_FLOATS * 4)

__global__ __launch_bounds__(256, 2) void kMain(
    const float* __restrict__ att_b1, const float* __restrict__ att_w2,
    const float* __restrict__ att_b2, float* __restrict__ out_ns)
{
    const int t  = threadIdx.x;
    const int b  = blockIdx.x >> 6;
    const int i  = blockIdx.x & 63;
    const int lane = t & 31, wid = t >> 5;
    const int tx = t & 15, ty = t >> 4;
    const int j0g = ty * 4, r0 = tx * 4;
    const int gid = lane >> 2, tid4 = lane & 3;
    const int wm  = (wid & 3) * 16;
    const int wnl = (wid >> 2) * 32;

    extern __shared__ float sm[];
    float*    sRA  = sm + SM_RA;
    float*    sP   = sm + SM_SP;
    uint32_t* sPAH = (uint32_t*)(sm + SM_PAH);   // [64][40] u32, perm8 pairs
    uint32_t* sAhi = (uint32_t*)(sm + SM_AH);    // [64][136] u32, perm8 pairs
    float*    sA   = sm + SM_SA;
    float*    sAW  = sm + SM_SAW;
    float*    sb1  = sm + SM_SB1;
    float*    sw2  = sm + SM_SW2;
    float*    sred = sm + SM_SRED;

    const int rowA = b * WW + i;
    sA [t] = g_A [rowA * DD + t];
    sAW[t] = g_AW[rowA * DD + t];
    sb1[t] = att_b1[t];
    sw2[t] = att_w2[t];
    __syncthreads();

    // ---- GEMM1: scalar fp32, 8 k-chunks of 32d, pipelined fills ----
    const float* btT = g_BtT + (size_t)b * DD * VV;
    float* hb[2] = { sRA, sRA + 4352 };
    float* rb[2] = { sRA + 2176, sRA + 6528 };
    const int fd = t >> 4;
    const int fc = (t & 15) * 4;

    float4 hpre[2];
    #pragma unroll
    for (int it = 0; it < 2; ++it) {
        const int d = it * 16 + fd;
        float4 v = *(const float4*)(btT + d * 64 + fc);
        const float sa = sA[d];
        v.x *= sa; v.y *= sa; v.z *= sa; v.w *= sa;
        *(float4*)&hb[0][d * PAD + fc] = v;
    }
    #pragma unroll
    for (int it = 0; it < 2; ++it)
        hpre[it] = *(const float4*)(btT + (32 + it * 16 + fd) * 64 + fc);
    #pragma unroll
    for (int s = 0; s < 2; ++s) {
        const uint32_t rB = smem_u32(rb[s]);
        #pragma unroll
        for (int it = 0; it < 2; ++it) {
            const int d = it * 16 + fd;
            cp_async16(rB + (uint32_t)(d * PAD + fc) * 4, g_relaT + (s * 32 + d) * 64 + fc);
        }
        CP_COMMIT();
    }

    ull c1[4][2];
    #pragma unroll
    for (int u = 0; u < 4; ++u) { c1[u][0] = 0ull; c1[u][1] = 0ull; }

    for (int kc = 0; kc < 8; ++kc) {
        if (kc < 7) { CP_WAIT1(); } else { CP_WAIT0(); }
        __syncthreads();
        const float* hh = hb[kc & 1];
        const float* rr = rb[kc & 1];
        #pragma unroll 4
        for (int d = 0; d < 32; ++d) {
            const float4 h4 = *(const float4*)&hh[d * PAD + j0g];
            const ulonglong2 r2 = *(const ulonglong2*)&rr[d * PAD + r0];
            const ull hp[4] = {pack2(h4.x), pack2(h4.y), pack2(h4.z), pack2(h4.w)};
            #pragma unroll
            for (int u = 0; u < 4; ++u) {
                c1[u][0] = fma2(hp[u], r2.x, c1[u][0]);
                c1[u][1] = fma2(hp[u], r2.y, c1[u][1]);
            }
        }
        __syncthreads();
        if (kc < 7) {
            float* hd = hb[(kc + 1) & 1];
            #pragma unroll
            for (int it = 0; it < 2; ++it) {
                const int d = it * 16 + fd;
                const float sa = sA[(kc + 1) * 32 + d];
                float4 v = hpre[it];
                v.x *= sa; v.y *= sa; v.z *= sa; v.w *= sa;
                *(float4*)&hd[d * PAD + fc] = v;
            }
            if (kc < 6) {
                #pragma unroll
                for (int it = 0; it < 2; ++it)
                    hpre[it] = *(const float4*)(btT + ((kc + 2) * 32 + it * 16 + fd) * 64 + fc);
                const uint32_t rB = smem_u32(rb[kc & 1]);
                #pragma unroll
                for (int it = 0; it < 2; ++it) {
                    const int d = it * 16 + fd;
                    cp_async16(rB + (uint32_t)(d * PAD + fc) * 4,
                               g_relaT + ((kc + 2) * 32 + d) * 64 + fc);
                }
                CP_COMMIT();
            }
        }
    }
    #pragma unroll
    for (int u = 0; u < 4; ++u) {
        const float2 lo = unpack2(c1[u][0]);
        const float2 hi = unpack2(c1[u][1]);
        *(float4*)&sP[(j0g + u) * PAD + r0] = make_float4(lo.x, lo.y, hi.x, hi.y);
    }
    __syncthreads();

    // RW full image ([256][40] u32, perm8 rows) -> RA; overlaps softmax
    {
        const uint32_t hB = smem_u32(sRA);
        #pragma unroll
        for (int it = 0; it < 8; ++it) {
            const int idx = it * 256 + t;   // 2048 uint4
            const int n  = idx >> 3;
            const int q4 = (idx & 7) * 4;
            cp_async16(hB + (uint32_t)(n * 160 + q4 * 4), g_rwbHi + n * 32 + q4);
        }
        CP_COMMIT();
    }

    // ---- softmax + permuted P pair pack ----
    {
        const int j = t >> 2, q = t & 3;
        const float nul = sP[j * PAD + 63];
        float v[16];
        float mx = -1e30f;
        #pragma unroll
        for (int m = 0; m < 16; ++m) {
            float s = sP[j * PAD + q * 16 + m];
            s = (s <= nul) ? -1e10f : s;
            v[m] = s;
            mx = fmaxf(mx, s);
        }
        mx = fmaxf(mx, __shfl_xor_sync(0xffffffffu, mx, 1));
        mx = fmaxf(mx, __shfl_xor_sync(0xffffffffu, mx, 2));
        float se = 0.0f;
        #pragma unroll
        for (int m = 0; m < 16; ++m) { v[m] = expf(v[m] - mx); se += v[m]; }
        se += __shfl_xor_sync(0xffffffffu, se, 1);
        se += __shfl_xor_sync(0xffffffffu, se, 2);
        const float inv = 1.0f / se;
        #pragma unroll
        for (int m = 0; m < 16; ++m) { v[m] *= inv; sP[j * PAD + q * 16 + m] = v[m]; }
        #pragma unroll
        for (int mm = 0; mm < 8; ++mm) {
            const int slot = q * 8 + ((mm & 3) << 1) + (mm >> 2);
            sPAH[j * 40 + slot] = pkbf2(v[2 * mm], v[2 * mm + 1]);
        }
    }
    __syncthreads();

    const size_t ns_base = ((size_t)(b * NN + i * VV)) * RR;
    #pragma unroll
    for (int it = 0; it < 16; ++it) {
        const int l = it * 256 + t;
        out_ns[ns_base + (size_t)(l >> 6) * RR + (l & 63)] = sP[(l >> 6) * PAD + (l & 63)];
    }
    CP_WAIT0();
    __syncthreads();

    // ---- GEMM2: PV = P @ RW, bf16, 4 n-chunks, LDS.64 fragments ----
    const uint32_t* rwH = (const uint32_t*)sRA;
    const int pr0 = (wm + gid) * 40;
    const int pr1 = (wm + gid + 8) * 40;
    const int row0 = wm + gid, row1 = wm + gid + 8;
    const float* bwr0 = g_BW + (size_t)(b * VV + row0) * DD;
    const float* bwr1 = g_BW + (size_t)(b * VV + row1) * DD;

    for (int c = 0; c < 4; ++c) {
        float a2[4][4];
        #pragma unroll
        for (int nt = 0; nt < 4; ++nt)
            #pragma unroll
            for (int e = 0; e < 4; ++e) a2[nt][e] = 0.0f;

        #pragma unroll
        for (int ks = 0; ks < 4; ++ks) {
            const int np = ks * 8 + 2 * tid4;
            const ull A0 = *(const ull*)&sPAH[pr0 + np];
            const ull A1 = *(const ull*)&sPAH[pr1 + np];
            #pragma unroll
            for (int nt = 0; nt < 4; ++nt) {
                const int n = c * 64 + wnl + nt * 8 + gid;
                const ull B = *(const ull*)&rwH[n * 40 + np];
                mma_bf16(a2[nt], lo32(A0), lo32(A1), hi32(A0), hi32(A1), lo32(B), hi32(B));
            }
        }

        #pragma unroll
        for (int nt = 0; nt < 4; ++nt) {
            const int col = c * 64 + wnl + nt * 8 + 2 * tid4;
            const float aw0 = sAW[col], aw1v = sAW[col + 1];
            const float2 bw0 = *(const float2*)(bwr0 + col);
            const float2 bw1 = *(const float2*)(bwr1 + col);
            const uint32_t u0 = pkbf2(tanh_fast(a2[nt][0] + aw0 + bw0.x),
                                      tanh_fast(a2[nt][1] + aw1v + bw0.y));
            const uint32_t u1 = pkbf2(tanh_fast(a2[nt][2] + aw0 + bw1.x),
                                      tanh_fast(a2[nt][3] + aw1v + bw1.y));
            const int p = col >> 1;
            sAhi[row0 * 136 + perm8(p)] = u0;
            sAhi[row1 * 136 + perm8(p)] = u1;
        }
    }
    __syncthreads();   // sAhi complete; RA free

    // w1 chunk 0 fill ([64][136] u32 in RA)
    {
        const uint32_t wB = smem_u32(sRA);
        #pragma unroll
        for (int it = 0; it < 8; ++it) {
            const int idx = it * 256 + t;   // 2048 uint4
            const int n  = idx >> 5;
            const int q4 = (idx & 31) * 4;
            cp_async16(wB + (uint32_t)(n * 544 + q4 * 4), g_w1bT + n * 128 + q4);
        }
        CP_COMMIT();
    }

    // ---- GEMM3: 4 n-chunks of 64 cols, A = bf16-hi, LDS.64 fragments ----
    const int ar0 = (wm + gid) * 136;
    const int ar1 = (wm + gid + 8) * 136;
    const uint32_t* wb = (const uint32_t*)sRA;
    float p0 = 0.0f, p1 = 0.0f;

    for (int c = 0; c < 4; ++c) {
        CP_WAIT0();
        __syncthreads();

        float a3[4][4];
        #pragma unroll
        for (int nt = 0; nt < 4; ++nt)
            #pragma unroll
            for (int e = 0; e < 4; ++e) a3[nt][e] = 0.0f;

        #pragma unroll 4
        for (int ks = 0; ks < 16; ++ks) {
            const int np = ks * 8 + 2 * tid4;
            const ull A0 = *(const ull*)&sAhi[ar0 + np];
            const ull A1 = *(const ull*)&sAhi[ar1 + np];
            #pragma unroll
            for (int nt = 0; nt < 4; ++nt) {
                const int nl = wnl + nt * 8 + gid;
                const ull B = *(const ull*)&wb[nl * 136 + np];
                mma_bf16(a3[nt], lo32(A0), lo32(A1), hi32(A0), hi32(A1), lo32(B), hi32(B));
            }
        }
        __syncthreads();

        if (c < 3) {
            const uint32_t wB = smem_u32(sRA);
            #pragma unroll
            for (int it = 0; it < 8; ++it) {
                const int idx = it * 256 + t;
                const int n  = idx >> 5;
                const int q4 = (idx & 31) * 4;
                cp_async16(wB + (uint32_t)(n * 544 + q4 * 4),
                           g_w1bT + (size_t)((c + 1) * 64 + n) * 128 + q4);
            }
            CP_COMMIT();
        }

        #pragma unroll
        for (int nt = 0; nt < 4; ++nt) {
            const int col = c * 64 + wnl + nt * 8 + 2 * tid4;
            p0 = fmaf(tanh_fast(a3[nt][0] + sb1[col]),     sw2[col],     p0);
            p0 = fmaf(tanh_fast(a3[nt][1] + sb1[col + 1]), sw2[col + 1], p0);
            p1 = fmaf(tanh_fast(a3[nt][2] + sb1[col]),     sw2[col],     p1);
            p1 = fmaf(tanh_fast(a3[nt][3] + sb1[col + 1]), sw2[col + 1], p1);
        }
    }

    // ---- reduce att partial sums ----
    p0 += __shfl_xor_sync(0xffffffffu, p0, 1);
    p0 += __shfl_xor_sync(0xffffffffu, p0, 2);
    p1 += __shfl_xor_sync(0xffffffffu, p1, 1);
    p1 += __shfl_xor_sync(0xffffffffu, p1, 2);

    if (wid < 4) {
        if (tid4 == 0) { sred[wm + gid] = p0; sred[wm + gid + 8] = p1; }
    }
    __syncthreads();
    if (wid >= 4) {
        if (tid4 == 0) { sred[wm + gid] += p0; sred[wm + gid + 8] += p1; }
    }
    __syncthreads();

    // att out + exp weights (reuse sred as weights)
    if (t < 64) {
        const float av = sred[t] + att_b2[0];
        g_att[b * NN + i * VV + t] = av;
        sred[t] = expf(av);
    }
    __syncthreads();

    // ---- in-kernel fuse accumulation: num[b,d] += sum_n w_n * tv[n,d] ----
    {
        const int sl = perm8(t >> 1);
        const int sh = (t & 1) * 16;
        float acc = 0.0f;
        #pragma unroll 8
        for (int n = 0; n < 64; ++n) {
            const uint32_t u = sAhi[n * 136 + sl];
            acc = fmaf(sred[n], bf16bits_f((u >> sh) & 0xFFFFu), acc);
        }
        atomicAdd(&g_fuseN[b * DD + t], acc);
        if (t == 0) {
            float z = 0.0f;
            #pragma unroll 8
            for (int n = 0; n < 64; ++n) z += sred[n];
            atomicAdd(&g_Z[b], z);
        }
    }
}

__global__ __launch_bounds__(256) void kAtt(float* __restrict__ out_attn)
{
    const int b = blockIdx.x, t = threadIdx.x;
    __shared__ float red[8];
    float vals[16];
    float mx = -1e30f;
    #pragma unroll
    for (int it = 0; it < 16; ++it) {
        vals[it] = g_att[b * NN + it * 256 + t];
        mx = fmaxf(mx, vals[it]);
    }
    #pragma unroll
    for (int o = 16; o; o >>= 1) mx = fmaxf(mx, __shfl_xor_sync(0xffffffffu, mx, o));
    if ((t & 31) == 0) red[t >> 5] = mx;
    __syncthreads();
    float bm = red[0];
    #pragma unroll
    for (int w = 1; w < 8; ++w) bm = fmaxf(bm, red[w]);
    __syncthreads();
    float s = 0.0f;
    #pragma unroll
    for (int it = 0; it < 16; ++it) { vals[it] = expf(vals[it] - bm); s += vals[it]; }
    #pragma unroll
    for (int o = 16; o; o >>= 1) s += __shfl_xor_sync(0xffffffffu, s, o);
    if ((t & 31) == 0) red[t >> 5] = s;
    __syncthreads();
    float bs = 0.0f;
    #pragma unroll
    for (int w = 0; w < 8; ++w) bs += red[w];
    const float inv = 1.0f / bs;
    #pragma unroll
    for (int it = 0; it < 16; ++it)
        out_attn[b * NN + it * 256 + t] = vals[it] * inv;
}

__global__ __launch_bounds__(256) void kLogits(
    float* __restrict__ out, const float* __restrict__ ow, const float* __restrict__ ob)
{
    const int b = blockIdx.x, t = threadIdx.x;
    __shared__ float red[8];
    float v = g_fuseN[b * DD + t] * ow[t];
    #pragma unroll
    for (int o = 16; o; o >>= 1) v += __shfl_xor_sync(0xffffffffu, v, o);
    if ((t & 31) == 0) red[t >> 5] = v;
    __syncthreads();
    if (t == 0) {
        float s = 0.0f;
        #pragma unroll
        for (int w = 0; w < 8; ++w) s += red[w];
        out[b] = s / g_Z[b] + ob[0];
    }
}

extern "C" void kernel_launch(void* const* d_in, const int* in_sizes, int n_in,
                              void* d_out, int out_size)
{
    const int*   head = (const int*)d_in[0];
    const int*   tail = (const int*)d_in[1];
    const float* emb  = (const float*)d_in[2];
    const float* rela = (const float*)d_in[3];
    const float* fc_w = (const float*)d_in[4];
    const float* fc_b = (const float*)d_in[5];
    const float* aw1  = (const float*)d_in[6];
    const float* ab1  = (const float*)d_in[7];
    const float* aw2  = (const float*)d_in[8];
    const float* ab2  = (const float*)d_in[9];
    const float* ow   = (const float*)d_in[10];
    const float* ob   = (const float*)d_in[11];

    float* out        = (float*)d_out;
    float* out_logits = out;
    float* out_attn   = out + BB;
    float* out_ns     = out + BB + BB * NN;

    cudaFuncSetAttribute(kMain, cudaFuncAttributeMaxDynamicSharedMemorySize, SMEM_M_BYTES);

    kPre   <<<132,   256>>>(head, tail, emb, rela, fc_w, fc_b);
    kW1T   <<<128,   256>>>(aw1);
    kRWT   <<<32,    256>>>();
    kMain  <<<BB*WW, 256, SMEM_M_BYTES>>>(ab1, aw2, ab2, out_ns);
    kAtt   <<<BB,    256>>>(out_attn);
    kLogits<<<BB,    256>>>(out_logits, ow, ob);
}